// round 6
// baseline (speedup 1.0000x reference)
#include <cuda_runtime.h>
#include <cstdint>

// Embedding gather: out[token, :] = weight[idx[token], :]
// idx: [8192] int32, weight: [32000, 512] f32, out: [8192, 512] f32
//
// R3 shape (128-thr CTAs, 4 tokens/CTA, MLP=4, no smem) + L2 cache
// policies: weight reads L2::evict_last (keep gathered rows resident
// across graph replays), output stores L2::evict_first (don't let the
// 16 MB write stream thrash the weight working set).

static constexpr int VEC_PER_ROW    = 128;  // 512 f32 = 128 float4
static constexpr int TOKENS_PER_CTA = 4;
static constexpr int THREADS        = 128;

__global__ void __launch_bounds__(THREADS, 16)
embedding_gather_kernel(const int* __restrict__ idx,
                        const float4* __restrict__ weight,
                        float4* __restrict__ out)
{
    const int tid        = threadIdx.x;            // vec within row
    const int base_token = blockIdx.x * TOKENS_PER_CTA;

    uint64_t pol_last, pol_first;
    asm("createpolicy.fractional.L2::evict_last.b64 %0, 1.0;"  : "=l"(pol_last));
    asm("createpolicy.fractional.L2::evict_first.b64 %0, 1.0;" : "=l"(pol_first));

    // Independent index loads (warp-broadcast, cached).
    int rows[TOKENS_PER_CTA];
#pragma unroll
    for (int k = 0; k < TOKENS_PER_CTA; k++)
        rows[k] = __ldg(&idx[base_token + k]);

    // Front-batched independent gathers (MLP=4), weight kept L2-resident.
    float4 v[TOKENS_PER_CTA];
#pragma unroll
    for (int k = 0; k < TOKENS_PER_CTA; k++) {
        const float4* p = weight + (long long)rows[k] * VEC_PER_ROW + tid;
        asm volatile(
            "ld.global.nc.L2::cache_hint.v4.f32 {%0,%1,%2,%3}, [%4], %5;"
            : "=f"(v[k].x), "=f"(v[k].y), "=f"(v[k].z), "=f"(v[k].w)
            : "l"(p), "l"(pol_last));
    }

    // Streaming stores, evict-first so they don't displace weight rows.
#pragma unroll
    for (int k = 0; k < TOKENS_PER_CTA; k++) {
        float4* p = out + (long long)(base_token + k) * VEC_PER_ROW + tid;
        asm volatile(
            "st.global.L2::cache_hint.v4.f32 [%0], {%1,%2,%3,%4}, %5;"
            :: "l"(p), "f"(v[k].x), "f"(v[k].y), "f"(v[k].z), "f"(v[k].w),
               "l"(pol_first)
            : "memory");
    }
}

extern "C" void kernel_launch(void* const* d_in, const int* in_sizes, int n_in,
                              void* d_out, int out_size)
{
    const int*   idx    = (const int*)d_in[0];    // x: [4, 2048] int32
    const float* weight = (const float*)d_in[1];  // [32000, 512] f32
    float*       out    = (float*)d_out;          // [4, 2048, 512] f32

    const int n_tokens = in_sizes[0];             // 8192
    const int n_ctas   = n_tokens / TOKENS_PER_CTA; // 2048

    embedding_gather_kernel<<<n_ctas, THREADS>>>(
        idx, (const float4*)weight, (float4*)out);
}